// round 13
// baseline (speedup 1.0000x reference)
#include <cuda_runtime.h>
#include <cuda_bf16.h>
#include <cstdint>
#include <math.h>

#define HW    3136
#define WIMG  56
#define CDIM  512
#define KCMP  1024          // compact split storage: hi rows [0,512), lo rows [512,1024)
#define NH    16
#define BATCH 8

// ---------------- device scratch (no allocation allowed) ----------------
__device__ __align__(128) float g_qkv[(size_t)BATCH * 3 * CDIM * HW];  // (B,1536,3136)
__device__ __align__(128) float g_ctx[(size_t)BATCH * CDIM * HW];      // attention out
__device__ __align__(128) __nv_bfloat16 g_xe[(size_t)BATCH * KCMP * HW];   // x hi|lo
__device__ __align__(128) __nv_bfloat16 g_ce[(size_t)BATCH * KCMP * HW];   // ctx hi|lo
__device__ __align__(128) __nv_bfloat16 g_wqkv[(size_t)3 * CDIM * KCMP];   // (1536 x 1024) hi|lo
__device__ __align__(128) __nv_bfloat16 g_wproj[(size_t)CDIM * KCMP];      // (512 x 1024) hi|lo

// ---------------- PTX helpers (sm_80-baseline only) ----------------
__device__ __forceinline__ uint32_t smem_u32(const void* p) {
    uint32_t a;
    asm("{ .reg .u64 t; cvta.to.shared.u64 t, %1; cvt.u32.u64 %0, t; }" : "=r"(a) : "l"(p));
    return a;
}
__device__ __forceinline__ void cp16(uint32_t dst, const void* src) {
    asm volatile("cp.async.cg.shared.global [%0], [%1], 16;" :: "r"(dst), "l"(src));
}
__device__ __forceinline__ void cp16z(uint32_t dst, const void* src, bool pred) {
    int sz = pred ? 16 : 0;
    asm volatile("cp.async.cg.shared.global [%0], [%1], 16, %2;" :: "r"(dst), "l"(src), "r"(sz));
}
__device__ __forceinline__ void cp_commit() { asm volatile("cp.async.commit_group;" ::: "memory"); }
template <int N> __device__ __forceinline__ void cp_wait() { asm volatile("cp.async.wait_group %0;" :: "n"(N) : "memory"); }

#define LDSM4(r, a) \
    asm volatile("ldmatrix.sync.aligned.m8n8.x4.shared.b16 {%0,%1,%2,%3}, [%4];" \
        : "=r"((r)[0]), "=r"((r)[1]), "=r"((r)[2]), "=r"((r)[3]) : "r"(a))
#define LDSM4T(r, a) \
    asm volatile("ldmatrix.sync.aligned.m8n8.x4.trans.shared.b16 {%0,%1,%2,%3}, [%4];" \
        : "=r"((r)[0]), "=r"((r)[1]), "=r"((r)[2]), "=r"((r)[3]) : "r"(a))
#define MMA16816(d, a, b0, b1) \
    asm volatile("mma.sync.aligned.m16n8k16.row.col.f32.bf16.bf16.f32 " \
        "{%0,%1,%2,%3}, {%4,%5,%6,%7}, {%8,%9}, {%0,%1,%2,%3};" \
        : "+f"((d)[0]), "+f"((d)[1]), "+f"((d)[2]), "+f"((d)[3]) \
        : "r"((a)[0]), "r"((a)[1]), "r"((a)[2]), "r"((a)[3]), "r"(b0), "r"(b1))

// ---------------------------------------------------------------------------
// Conversion: fp32 -> compact split bf16 (hi plane [0,512), lo plane [512,1024))
// ---------------------------------------------------------------------------
__global__ void __launch_bounds__(256) expand_x(const float* __restrict__ src,
                                                __nv_bfloat16* __restrict__ dst) {
    size_t i = ((size_t)blockIdx.x * 256 + threadIdx.x) * 4;
    const size_t plane = (size_t)CDIM * HW;
    size_t b = i / plane, r = i - b * plane;
    float4 v = *(const float4*)(src + i);
    __nv_bfloat16 h0 = __float2bfloat16(v.x), h1 = __float2bfloat16(v.y);
    __nv_bfloat16 h2 = __float2bfloat16(v.z), h3 = __float2bfloat16(v.w);
    __nv_bfloat162 hA; hA.x = h0; hA.y = h1;
    __nv_bfloat162 hB; hB.x = h2; hB.y = h3;
    __nv_bfloat162 lA, lB;
    lA.x = __float2bfloat16(v.x - __bfloat162float(h0));
    lA.y = __float2bfloat16(v.y - __bfloat162float(h1));
    lB.x = __float2bfloat16(v.z - __bfloat162float(h2));
    lB.y = __float2bfloat16(v.w - __bfloat162float(h3));
    __nv_bfloat16* base = dst + b * (size_t)KCMP * HW + r;
    *(__nv_bfloat162*)(base) = hA;                      *(__nv_bfloat162*)(base + 2) = hB;
    *(__nv_bfloat162*)(base + (size_t)512 * HW) = lA;   *(__nv_bfloat162*)(base + (size_t)512 * HW + 2) = lB;
}

__global__ void __launch_bounds__(256) expand_w(const float* __restrict__ w,
                                                __nv_bfloat16* __restrict__ we, int qrows) {
    int i = blockIdx.x * 256 + threadIdx.x;
    int row = i >> 9, k = i & 511;
    float v = w[i];
    if (row < qrows) v *= 0.17677669529663688f;   // 1/sqrt(32) folded into W_q
    __nv_bfloat16 h = __float2bfloat16(v);
    __nv_bfloat16 l = __float2bfloat16(v - __bfloat162float(h));
    __nv_bfloat16* o = we + (size_t)row * KCMP;
    o[k] = h; o[512 + k] = l;
}

// ---------------------------------------------------------------------------
// HMMA GEMM: C[b](Nout x 3136) = sum of 3 split terms over 48 K-chunks of 32:
//   chunks  0-15: W_hi x X_hi,  16-31: W_lo x X_hi,  32-47: W_hi x X_lo
// 128x128 tile, 256 thr (8 warps of 32x64), 3-stage cp.async, 1 barrier/chunk.
// ---------------------------------------------------------------------------
#define A_STRIDE_B 80
#define B_STRIDE_B 272
#define A_STAGE (128 * A_STRIDE_B)       // 10240
#define B_STAGE (32 * B_STRIDE_B)        // 8704
#define STAGE_B (A_STAGE + B_STAGE)      // 18944
#define NCHUNK  48
#define GEMM_SMEM (3 * STAGE_B)          // 56832

template<bool BIAS>
__global__ void __launch_bounds__(256) gemm_mma(
    const __nv_bfloat16* __restrict__ A, const __nv_bfloat16* __restrict__ Bx,
    float* __restrict__ C, const float* __restrict__ bias, int Nout)
{
    extern __shared__ __align__(16) char smem[];
    const int tid = threadIdx.x;
    const int wid = tid >> 5, lane = tid & 31;
    const int wm = wid >> 1, wn = wid & 1;
    const int n0 = blockIdx.x * 128;
    const int m0 = blockIdx.y * 128;
    const int b  = blockIdx.z;
    const bool full = (n0 + 128 <= HW);

    const uint32_t sb = smem_u32(smem);
    const __nv_bfloat16* Ag = A + (size_t)m0 * KCMP;
    const __nv_bfloat16* Bg = Bx + (size_t)b * KCMP * HW + n0;

    float acc[2][8][4];
    #pragma unroll
    for (int i = 0; i < 2; i++)
        #pragma unroll
        for (int j = 0; j < 8; j++)
            #pragma unroll
            for (int k = 0; k < 4; k++) acc[i][j][k] = 0.f;

    auto load = [&](int c, int s) {
        int reg = c >> 4;                              // 0,1,2
        int aoff = ((reg == 1) ? 512 : 0) + (c & 15) * 32;   // W: hi,lo,hi
        int boff = ((reg == 2) ? 512 : 0) + (c & 15) * 32;   // X: hi,hi,lo
        uint32_t as = sb + s * STAGE_B;
        uint32_t bs = as + A_STAGE;
        #pragma unroll
        for (int it = 0; it < 2; it++) {               // A: 128 rows x 4x16B
            int q = tid + it * 256;
            int row = q >> 2, seg = q & 3;
            cp16(as + row * A_STRIDE_B + seg * 16,
                 Ag + (size_t)row * KCMP + aoff + seg * 8);
        }
        #pragma unroll
        for (int it = 0; it < 2; it++) {               // B: 32 rows x 16x16B
            int q = tid + it * 256;
            int row = q >> 4, seg = q & 15;
            bool p = full || (seg < 8);
            const __nv_bfloat16* src = Bg + (size_t)(boff + row) * HW + (p ? seg * 8 : 0);
            cp16z(bs + row * B_STRIDE_B + seg * 16, src, p);
        }
        cp_commit();
    };

    load(0, 0);
    load(1, 1);
    for (int i = 0; i < NCHUNK; i++) {
        int s = i % 3;
        if (i + 1 < NCHUNK) cp_wait<1>(); else cp_wait<0>();
        __syncthreads();
        if (i + 2 < NCHUNK) load(i + 2, (i + 2) % 3);

        uint32_t as = sb + s * STAGE_B;
        uint32_t bs = as + A_STAGE;
        #pragma unroll
        for (int kk = 0; kk < 2; kk++) {
            uint32_t af[2][4], bf[4][4];
            #pragma unroll
            for (int im = 0; im < 2; im++) {
                uint32_t addr = as + (wm * 32 + im * 16 + (lane & 15)) * A_STRIDE_B
                              + kk * 32 + ((lane >> 4) << 4);
                LDSM4(af[im], addr);
            }
            #pragma unroll
            for (int jn = 0; jn < 4; jn++) {
                uint32_t addr = bs + (kk * 16 + (lane & 15)) * B_STRIDE_B
                              + (wn * 64 + jn * 16 + ((lane >> 4) << 3)) * 2;
                LDSM4T(bf[jn], addr);
            }
            #pragma unroll
            for (int im = 0; im < 2; im++)
                #pragma unroll
                for (int jn = 0; jn < 4; jn++) {
                    MMA16816(acc[im][jn * 2 + 0], af[im], bf[jn][0], bf[jn][1]);
                    MMA16816(acc[im][jn * 2 + 1], af[im], bf[jn][2], bf[jn][3]);
                }
        }
    }

    // epilogue
    const int r0 = wm * 32 + (lane >> 2);
    const int cb = wn * 64 + (lane & 3) * 2;
    const int nvalid = full ? 128 : 64;
    #pragma unroll
    for (int im = 0; im < 2; im++) {
        int rowA = m0 + r0 + im * 16;
        float bv0 = BIAS ? bias[rowA] : 0.f;
        float bv1 = BIAS ? bias[rowA + 8] : 0.f;
        float* p0 = C + (size_t)b * Nout * HW + (size_t)rowA * HW + n0;
        float* p1 = p0 + (size_t)8 * HW;
        #pragma unroll
        for (int jn = 0; jn < 8; jn++) {
            int col = cb + jn * 8;
            if (col < nvalid) {
                *(float2*)(p0 + col) = make_float2(acc[im][jn][0] + bv0, acc[im][jn][1] + bv0);
                *(float2*)(p1 + col) = make_float2(acc[im][jn][2] + bv1, acc[im][jn][3] + bv1);
            }
        }
    }
}

// ---------------------------------------------------------------------------
// Neighborhood attention: kv transposed to [pos][36] so each neighbor's 32
// dims are 8x LDS.128 (conflict-free: 8-lane phase banks 4*pos+d distinct).
// ---------------------------------------------------------------------------
__global__ void __launch_bounds__(64) natten_kernel(const float* __restrict__ rpb)
{
    __shared__ float kv[196][36];
    __shared__ float rs[169];

    const int tile = blockIdx.x, head = blockIdx.y, b = blockIdx.z;
    const int ti = tile / 7, tj = tile % 7;
    const int i0 = ti * 8,   j0 = tj * 8;
    const int r0 = min(max(i0 - 3, 0), 42);
    const int c0 = min(max(j0 - 3, 0), 42);

    const size_t base = ((size_t)b * 1536 + head * 32) * HW;
    const float* qb = g_qkv + base;
    const float* kb = qb + (size_t)512 * HW;
    const float* vb = qb + (size_t)1024 * HW;
    const int tid = threadIdx.x;

    for (int t = tid; t < 169; t += 64) rs[t] = rpb[head * 169 + t];
    for (int t = tid; t < 196 * 32; t += 64) {
        int d = t / 196, pos = t - d * 196;
        kv[pos][d] = kb[(size_t)d * HW + (r0 + pos / 14) * WIMG + c0 + pos % 14];
    }

    const int ty = tid >> 3, tx = tid & 7;
    const int i = i0 + ty, j = j0 + tx;
    const int si = min(max(i - 3, 0), 49);
    const int sj = min(max(j - 3, 0), 49);
    const int rbase = (si - r0) * 14 + (sj - c0);
    const int boff  = (si - i + 6) * 13 + (sj - j + 6);

    float q[32];
    #pragma unroll
    for (int d = 0; d < 32; d++) q[d] = qb[(size_t)d * HW + i * WIMG + j];
    __syncthreads();

    float logit[49];
    #pragma unroll
    for (int a = 0; a < 7; a++)
        #pragma unroll
        for (int c = 0; c < 7; c++) {
            const float* row = kv[rbase + a * 14 + c];
            float acc = 0.f;
            #pragma unroll
            for (int d4 = 0; d4 < 8; d4++) {
                float4 kk = *(const float4*)(row + d4 * 4);
                acc += q[d4 * 4 + 0] * kk.x + q[d4 * 4 + 1] * kk.y
                     + q[d4 * 4 + 2] * kk.z + q[d4 * 4 + 3] * kk.w;
            }
            logit[a * 7 + c] = acc + rs[boff + a * 13 + c];
        }

    float mx = logit[0];
    #pragma unroll
    for (int t = 1; t < 49; t++) mx = fmaxf(mx, logit[t]);
    float s = 0.f;
    #pragma unroll
    for (int t = 0; t < 49; t++) { float e = __expf(logit[t] - mx); logit[t] = e; s += e; }
    const float inv = 1.f / s;

    __syncthreads();
    for (int t = tid; t < 196 * 32; t += 64) {
        int d = t / 196, pos = t - d * 196;
        kv[pos][d] = vb[(size_t)d * HW + (r0 + pos / 14) * WIMG + c0 + pos % 14];
    }
    __syncthreads();

    float out[32];
    #pragma unroll
    for (int d = 0; d < 32; d++) out[d] = 0.f;
    #pragma unroll
    for (int a = 0; a < 7; a++)
        #pragma unroll
        for (int c = 0; c < 7; c++) {
            const float w = logit[a * 7 + c];
            const float* row = kv[rbase + a * 14 + c];
            #pragma unroll
            for (int d4 = 0; d4 < 8; d4++) {
                float4 vv = *(const float4*)(row + d4 * 4);
                out[d4 * 4 + 0] += w * vv.x; out[d4 * 4 + 1] += w * vv.y;
                out[d4 * 4 + 2] += w * vv.z; out[d4 * 4 + 3] += w * vv.w;
            }
        }

    float* ob = g_ctx + ((size_t)b * 512 + head * 32) * HW + i * WIMG + j;
    #pragma unroll
    for (int d = 0; d < 32; d++) ob[(size_t)d * HW] = out[d] * inv;
}

// ---------------------------------------------------------------------------
extern "C" void kernel_launch(void* const* d_in, const int* in_sizes, int n_in,
                              void* d_out, int out_size)
{
    (void)in_sizes; (void)n_in; (void)out_size;
    const float* x      = (const float*)d_in[0];
    const float* qkv_w  = (const float*)d_in[1];
    const float* rpb    = (const float*)d_in[2];
    const float* proj_w = (const float*)d_in[3];
    const float* proj_b = (const float*)d_in[4];
    float* out = (float*)d_out;

    float *qkvp, *ctxp;
    __nv_bfloat16 *xe, *ce, *wq, *wp;
    cudaGetSymbolAddress((void**)&qkvp, g_qkv);
    cudaGetSymbolAddress((void**)&ctxp, g_ctx);
    cudaGetSymbolAddress((void**)&xe, g_xe);
    cudaGetSymbolAddress((void**)&ce, g_ce);
    cudaGetSymbolAddress((void**)&wq, g_wqkv);
    cudaGetSymbolAddress((void**)&wp, g_wproj);

    cudaFuncSetAttribute(gemm_mma<false>, cudaFuncAttributeMaxDynamicSharedMemorySize, GEMM_SMEM);
    cudaFuncSetAttribute(gemm_mma<true>,  cudaFuncAttributeMaxDynamicSharedMemorySize, GEMM_SMEM);

    // 0) precision-split conversions (compact hi|lo storage)
    expand_w<<<(3 * CDIM * CDIM) / 256, 256>>>(qkv_w, wq, 512);
    expand_w<<<(CDIM * CDIM) / 256, 256>>>(proj_w, wp, 0);
    expand_x<<<(BATCH * CDIM * HW) / 1024, 256>>>(x, xe);

    // 1) QKV GEMM (HMMA), q-scale folded into W
    gemm_mma<false><<<dim3(25, 12, BATCH), 256, GEMM_SMEM>>>(wq, xe, qkvp, nullptr, 1536);

    // 2) neighborhood attention
    natten_kernel<<<dim3(49, NH, BATCH), 64>>>(rpb);

    // 3) projection GEMM + bias, direct NCHW output
    expand_x<<<(BATCH * CDIM * HW) / 1024, 256>>>(ctxp, ce);
    gemm_mma<true><<<dim3(25, 4, BATCH), 256, GEMM_SMEM>>>(wp, ce, out, proj_b, 512);
}